// round 2
// baseline (speedup 1.0000x reference)
#include <cuda_runtime.h>
#include <stdint.h>

#define BATCH 2048
#define EPS 1e-5f

// ---------------- static scratch (no dynamic allocation allowed) ----------------
__device__ uint32_t           g_h1[BATCH * 28 * 28];   // stem output, 32 ch packed per pixel
__device__ unsigned long long g_h2[BATCH * 14 * 14];   // block1 output, 64 ch packed
__device__ unsigned long long g_h3[BATCH * 7 * 7];     // block2 output, 64 ch packed
__device__ uint32_t           g_w2p[64 * 9];           // sign(w2) packed: [o][tap], bit c
__device__ unsigned long long g_w3p[64 * 9];           // sign(w3) packed
__device__ unsigned long long g_wfcp[256 * 49];        // sign(w_fc) packed: [o][pixel], bit c
__device__ float g_inv1[32], g_inv2[64], g_inv3[64], g_inv4[256];

// ---------------- weight packing + BN scale precompute ----------------
__global__ void pack_kernel(const float* __restrict__ w2, const float* __restrict__ w3,
                            const float* __restrict__ wfc,
                            const float* __restrict__ g1, const float* __restrict__ v1,
                            const float* __restrict__ g2, const float* __restrict__ v2,
                            const float* __restrict__ g3, const float* __restrict__ v3,
                            const float* __restrict__ g4, const float* __restrict__ v4) {
    int idx = blockIdx.x * 256 + threadIdx.x;
    if (idx < 576) {                                   // w2: [64,32,3,3]
        int o = idx / 9, t = idx % 9;
        uint32_t bits = 0;
        for (int c = 0; c < 32; c++)
            bits |= (w2[o * 288 + c * 9 + t] >= 0.f ? 1u : 0u) << c;
        g_w2p[idx] = bits;
    } else if (idx < 1152) {                           // w3: [64,64,3,3]
        int j = idx - 576; int o = j / 9, t = j % 9;
        unsigned long long bits = 0;
        for (int c = 0; c < 64; c++)
            bits |= (unsigned long long)(w3[o * 576 + c * 9 + t] >= 0.f) << c;
        g_w3p[j] = bits;
    } else if (idx < 13696) {                          // w_fc: [256, 3136] (c*49 + p)
        int j = idx - 1152; int o = j / 49, p = j % 49;
        unsigned long long bits = 0;
        for (int c = 0; c < 64; c++)
            bits |= (unsigned long long)(wfc[o * 3136 + c * 49 + p] >= 0.f) << c;
        g_wfcp[j] = bits;
    } else if (idx < 13696 + 32) {
        int c = idx - 13696; g_inv1[c] = g1[c] / sqrtf(v1[c] + EPS);
    } else if (idx < 13728 + 64) {
        int c = idx - 13728; g_inv2[c] = g2[c] / sqrtf(v2[c] + EPS);
    } else if (idx < 13792 + 64) {
        int c = idx - 13792; g_inv3[c] = g3[c] / sqrtf(v3[c] + EPS);
    } else if (idx < 13856 + 256) {
        int c = idx - 13856; g_inv4[c] = g4[c] / sqrtf(v4[c] + EPS);
    }
}

// ---------------- stem: fp32 conv3x3(1->32) + BN + sign -> packed u32 ----------------
__global__ void __launch_bounds__(256) stem_kernel(const float* __restrict__ x,
                                                   const float* __restrict__ ws,
                                                   const float* __restrict__ m1,
                                                   const float* __restrict__ b1) {
    __shared__ float sw[288], sinv[32], sm[32], sb[32];
    int t = threadIdx.x;
    for (int i = t; i < 288; i += 256) sw[i] = ws[i];   // FIX: 288 > blockDim, must stride
    if (t < 32) { sinv[t] = g_inv1[t]; sm[t] = m1[t]; sb[t] = b1[t]; }
    __syncthreads();

    int idx = blockIdx.x * 256 + t;               // exactly 2048*784 threads
    int b = idx / 784, p = idx % 784;
    int y = p / 28, xx = p % 28;
    const float* xb = x + b * 784;

    float win[9];
#pragma unroll
    for (int dy = 0; dy < 3; dy++)
#pragma unroll
        for (int dx = 0; dx < 3; dx++) {
            int yy = y + dy - 1, xc = xx + dx - 1;
            win[dy * 3 + dx] = (yy >= 0 && yy < 28 && xc >= 0 && xc < 28) ? xb[yy * 28 + xc] : 0.f;
        }

    uint32_t bits = 0;
#pragma unroll 4
    for (int c = 0; c < 32; c++) {
        float s = 0.f;
#pragma unroll
        for (int k = 0; k < 9; k++) s += sw[c * 9 + k] * win[k];
        float v = (s - sm[c]) * sinv[c] + sb[c];   // clip(-1,1) preserves sign
        bits |= (v >= 0.f ? 1u : 0u) << c;
    }
    g_h1[idx] = bits;
}

// ---------------- block1: binary conv(32->64) + BN + maxpool2 + sign ----------------
__global__ void __launch_bounds__(256) conv2_kernel(const float* __restrict__ m2,
                                                    const float* __restrict__ b2) {
    __shared__ uint32_t swt[576];
    __shared__ float sinv[64], sm[64], sb[64];
    int t = threadIdx.x;
    for (int i = t; i < 576; i += 256) swt[i] = g_w2p[i];
    if (t < 64) { sinv[t] = g_inv2[t]; sm[t] = m2[t]; sb[t] = b2[t]; }
    __syncthreads();

    int idx = blockIdx.x * 256 + t;               // exactly 2048*196 threads
    int b = idx / 196, p = idx % 196;
    int oy = p / 14, ox = p % 14;
    const uint32_t* h = g_h1 + b * 784;

    int rbase = 2 * oy - 1, cbase = 2 * ox - 1;
    uint32_t win[16];
    int msk[16];                                   // 0 or -1 (applied to popc result)
    int rv[4], cv[4];
#pragma unroll
    for (int i = 0; i < 4; i++) {
        rv[i] = (rbase + i >= 0 && rbase + i < 28);
        cv[i] = (cbase + i >= 0 && cbase + i < 28);
    }
#pragma unroll
    for (int i = 0; i < 4; i++)
#pragma unroll
        for (int j = 0; j < 4; j++) {
            bool v = rv[i] && cv[j];
            msk[i * 4 + j] = v ? -1 : 0;
            win[i * 4 + j] = v ? h[(rbase + i) * 28 + (cbase + j)] : 0u;
        }
    int rc0 = rv[0] + rv[1] + rv[2], rc1 = rv[1] + rv[2] + rv[3];
    int cc0 = cv[0] + cv[1] + cv[2], cc1 = cv[1] + cv[2] + cv[3];
    float base[4] = { 32.f * (rc0 * cc0), 32.f * (rc0 * cc1),
                      32.f * (rc1 * cc0), 32.f * (rc1 * cc1) };

    unsigned long long obits = 0;
    for (int c = 0; c < 64; c++) {
        uint32_t wt[9];
#pragma unroll
        for (int k = 0; k < 9; k++) wt[k] = swt[c * 9 + k];
        float inv = sinv[c], mm = sm[c], bb = sb[c];
        float mx = -1e30f;
#pragma unroll
        for (int py = 0; py < 2; py++)
#pragma unroll
            for (int px = 0; px < 2; px++) {
                int acc = 0;
#pragma unroll
                for (int dy = 0; dy < 3; dy++)
#pragma unroll
                    for (int dx = 0; dx < 3; dx++) {
                        int wi = (py + dy) * 4 + (px + dx);
                        acc += __popc(win[wi] ^ wt[dy * 3 + dx]) & msk[wi];
                    }
                float dot = base[py * 2 + px] - 2.f * (float)acc;
                float val = (dot - mm) * inv + bb;
                mx = fmaxf(mx, val);
            }
        obits |= (unsigned long long)(mx >= 0.f) << c;
    }
    g_h2[idx] = obits;
}

// ---------------- block2: binary conv(64->64) + BN + maxpool2 + sign ----------------
__global__ void __launch_bounds__(256) conv3_kernel(const float* __restrict__ m3,
                                                    const float* __restrict__ b3) {
    __shared__ unsigned long long swt[576];
    __shared__ float sinv[64], sm[64], sb[64];
    int t = threadIdx.x;
    for (int i = t; i < 576; i += 256) swt[i] = g_w3p[i];
    if (t < 64) { sinv[t] = g_inv3[t]; sm[t] = m3[t]; sb[t] = b3[t]; }
    __syncthreads();

    int idx = blockIdx.x * 256 + t;               // exactly 2048*49 threads
    int b = idx / 49, p = idx % 49;
    int oy = p / 7, ox = p % 7;
    const unsigned long long* h = g_h2 + b * 196;

    int rbase = 2 * oy - 1, cbase = 2 * ox - 1;
    unsigned long long win[16];
    int msk[16];
    int rv[4], cv[4];
#pragma unroll
    for (int i = 0; i < 4; i++) {
        rv[i] = (rbase + i >= 0 && rbase + i < 14);
        cv[i] = (cbase + i >= 0 && cbase + i < 14);
    }
#pragma unroll
    for (int i = 0; i < 4; i++)
#pragma unroll
        for (int j = 0; j < 4; j++) {
            bool v = rv[i] && cv[j];
            msk[i * 4 + j] = v ? -1 : 0;
            win[i * 4 + j] = v ? h[(rbase + i) * 14 + (cbase + j)] : 0ull;
        }
    int rc0 = rv[0] + rv[1] + rv[2], rc1 = rv[1] + rv[2] + rv[3];
    int cc0 = cv[0] + cv[1] + cv[2], cc1 = cv[1] + cv[2] + cv[3];
    float base[4] = { 64.f * (rc0 * cc0), 64.f * (rc0 * cc1),
                      64.f * (rc1 * cc0), 64.f * (rc1 * cc1) };

    unsigned long long obits = 0;
    for (int c = 0; c < 64; c++) {
        unsigned long long wt[9];
#pragma unroll
        for (int k = 0; k < 9; k++) wt[k] = swt[c * 9 + k];
        float inv = sinv[c], mm = sm[c], bb = sb[c];
        float mx = -1e30f;
#pragma unroll
        for (int py = 0; py < 2; py++)
#pragma unroll
            for (int px = 0; px < 2; px++) {
                int acc = 0;
#pragma unroll
                for (int dy = 0; dy < 3; dy++)
#pragma unroll
                    for (int dx = 0; dx < 3; dx++) {
                        int wi = (py + dy) * 4 + (px + dx);
                        acc += __popcll(win[wi] ^ wt[dy * 3 + dx]) & msk[wi];
                    }
                float dot = base[py * 2 + px] - 2.f * (float)acc;
                float val = (dot - mm) * inv + bb;
                mx = fmaxf(mx, val);
            }
        obits |= (unsigned long long)(mx >= 0.f) << c;
    }
    g_h3[idx] = obits;
}

// ---------------- classifier: binary fc(3136->256) + BN + fp head(256->10) ----------------
__global__ void __launch_bounds__(256) fc_kernel(const float* __restrict__ m4,
                                                 const float* __restrict__ b4,
                                                 const float* __restrict__ w_head,
                                                 const float* __restrict__ b_head,
                                                 float* __restrict__ out) {
    __shared__ unsigned long long xrow[49];
    __shared__ float h4[256];
    int b = blockIdx.x, t = threadIdx.x;
    if (t < 49) xrow[t] = g_h3[b * 49 + t];
    __syncthreads();

    const unsigned long long* wr = g_wfcp + t * 49;
    int acc = 0;
#pragma unroll
    for (int p = 0; p < 49; p++) acc += __popcll(xrow[p] ^ wr[p]);
    float val = (float)(3136 - 2 * acc);
    h4[t] = (val - m4[t]) * g_inv4[t] + b4[t];
    __syncthreads();

    if (t < 10) {
        float s = b_head[t];
        const float* wh = w_head + t * 256;
#pragma unroll 8
        for (int c = 0; c < 256; c++) s += h4[c] * wh[c];
        out[b * 10 + t] = s;
    }
}

// ---------------- launch ----------------
extern "C" void kernel_launch(void* const* d_in, const int* in_sizes, int n_in,
                              void* d_out, int out_size) {
    const float* x      = (const float*)d_in[0];
    const float* w_stem = (const float*)d_in[1];
    const float* g1 = (const float*)d_in[2];
    const float* b1 = (const float*)d_in[3];
    const float* m1 = (const float*)d_in[4];
    const float* v1 = (const float*)d_in[5];
    const float* w2 = (const float*)d_in[6];
    const float* g2 = (const float*)d_in[7];
    const float* b2 = (const float*)d_in[8];
    const float* m2 = (const float*)d_in[9];
    const float* v2 = (const float*)d_in[10];
    const float* w3 = (const float*)d_in[11];
    const float* g3 = (const float*)d_in[12];
    const float* b3 = (const float*)d_in[13];
    const float* m3 = (const float*)d_in[14];
    const float* v3 = (const float*)d_in[15];
    const float* w_fc = (const float*)d_in[16];
    const float* g4 = (const float*)d_in[17];
    const float* b4 = (const float*)d_in[18];
    const float* m4 = (const float*)d_in[19];
    const float* v4 = (const float*)d_in[20];
    const float* w_head = (const float*)d_in[21];
    const float* b_head = (const float*)d_in[22];
    float* out = (float*)d_out;

    pack_kernel<<<56, 256>>>(w2, w3, w_fc, g1, v1, g2, v2, g3, v3, g4, v4);
    stem_kernel<<<(BATCH * 784) / 256, 256>>>(x, w_stem, m1, b1);
    conv2_kernel<<<(BATCH * 196) / 256, 256>>>(m2, b2);
    conv3_kernel<<<(BATCH * 49) / 256, 256>>>(m3, b3);
    fc_kernel<<<BATCH, 256>>>(m4, b4, w_head, b_head, out);
}